// round 3
// baseline (speedup 1.0000x reference)
#include <cuda_runtime.h>
#include <cuda_bf16.h>
#include <cstdint>

// ---------------- problem constants ----------------
#define BN 8192      // batch
#define DK 128       // dim
#define NCLS 2048    // label classes
__device__ __constant__ float c_dummy; // keep nvcc happy about empty cmem use
constexpr float INV_T = 1.0f / 0.07f;  // 14.285714...

// ---------------- device scratch (no allocs allowed) ----------------
__device__ __nv_bfloat16 g_Ebf[BN * DK];   // bf16 copy of embeddings (2 MB)
__device__ float g_S[NCLS * DK];           // per-class sums (1 MB)
__device__ int   g_cnt[NCLS];              // per-class counts
__device__ float g_Z[BN];                  // per-row shifted exp sums
__device__ int   g_lab[BN];                // normalized int32 labels
__device__ float g_num;                    // sum of row means
__device__ int   g_den;                    // count of rows with positives
__device__ int   g_odd;                    // label dtype detection flag

// ---------------- K0a: zero scratch + fp32->bf16 convert ----------------
__global__ void k_init(const float* __restrict__ E) {
    int idx = blockIdx.x * blockDim.x + threadIdx.x;     // 1,048,576 threads
    if (idx < BN * DK)  g_Ebf[idx] = __float2bfloat16(E[idx]);
    if (idx < NCLS * DK) g_S[idx] = 0.0f;
    if (idx < NCLS)      g_cnt[idx] = 0;
    if (idx < BN)        g_Z[idx] = 0.0f;
    if (idx == 0) { g_num = 0.0f; g_den = 0; g_odd = 0; }
}

// ---------------- K0b: detect labels dtype (int32 vs int64) ----------------
// Safe: we only read the first 8192 int32 words, which exist in both layouts.
// int64 (LE) => every odd word is the zero high-half. int32 => odd words are
// random labels, P(all zero) ~ (1/2048)^4096 == 0.
__global__ void k_detect(const int* __restrict__ lab32) {
    int idx = blockIdx.x * blockDim.x + threadIdx.x;     // 8192 threads
    if (idx < BN && (idx & 1) && lab32[idx] != 0) atomicOr(&g_odd, 1);
}

// ---------------- K0c: normalize labels to int32 ----------------
__global__ void k_norm(const void* __restrict__ labp) {
    int idx = blockIdx.x * blockDim.x + threadIdx.x;
    if (idx >= BN) return;
    int v;
    if (g_odd) v = ((const int*)labp)[idx];                       // int32 data
    else       v = (int)(((const long long*)labp)[idx]);          // int64 data
    g_lab[idx] = v;
}

// ---------------- K1: class sums + counts ----------------
__global__ void k_csum(const float* __restrict__ E) {
    int idx = blockIdx.x * blockDim.x + threadIdx.x;     // BN*DK threads
    if (idx >= BN * DK) return;
    int row = idx >> 7, d = idx & 127;
    int c = g_lab[row];
    atomicAdd(&g_S[c * DK + d], E[idx]);
    if (d == 0) atomicAdd(&g_cnt[c], 1);
}

// ---------------- mma / ldmatrix helpers ----------------
__device__ __forceinline__ uint32_t smem_u32(const void* p) {
    return (uint32_t)__cvta_generic_to_shared(p);
}
__device__ __forceinline__ void ldsm_x4(uint32_t* r, const void* p) {
    uint32_t a = smem_u32(p);
    asm volatile("ldmatrix.sync.aligned.m8n8.x4.shared.b16 {%0,%1,%2,%3}, [%4];\n"
                 : "=r"(r[0]), "=r"(r[1]), "=r"(r[2]), "=r"(r[3]) : "r"(a));
}
__device__ __forceinline__ void ldsm_x2(uint32_t* r, const void* p) {
    uint32_t a = smem_u32(p);
    asm volatile("ldmatrix.sync.aligned.m8n8.x2.shared.b16 {%0,%1}, [%2];\n"
                 : "=r"(r[0]), "=r"(r[1]) : "r"(a));
}
__device__ __forceinline__ void mma16816(float* c, const uint32_t* a, const uint32_t* b) {
    asm volatile(
        "mma.sync.aligned.m16n8k16.row.col.f32.bf16.bf16.f32 "
        "{%0,%1,%2,%3}, {%4,%5,%6,%7}, {%8,%9}, {%0,%1,%2,%3};\n"
        : "+f"(c[0]), "+f"(c[1]), "+f"(c[2]), "+f"(c[3])
        : "r"(a[0]), "r"(a[1]), "r"(a[2]), "r"(a[3]), "r"(b[0]), "r"(b[1]));
}

// ---------------- K2: main GEMM + streaming exp -> Z ----------------
// Block tile: 128 rows x 128 cols, 8 warps as 4(m) x 2(n). Each block handles
// 8 j-tiles (1024 cols). Grid (64 row-tiles, 8 j-splits) = 512 CTAs.
#define SKEW 136                       // smem row stride in bf16 elems (272 B)
#define JT_PER_BLK 8
#define K2_SMEM (2 * 128 * SKEW * 2)   // 69632 B

__global__ void __launch_bounds__(256, 2) k_main() {
    extern __shared__ __align__(16) char smem_raw[];
    __nv_bfloat16* As = (__nv_bfloat16*)smem_raw;
    __nv_bfloat16* Bs = As + 128 * SKEW;

    const int tid  = threadIdx.x;
    const int warp = tid >> 5, lane = tid & 31;
    const int wm = warp >> 1;      // 0..3  (rows wm*32..+32)
    const int wn = warp & 1;       // 0..1  (cols wn*64..+64)
    const int rowbase = blockIdx.x * 128;

    // load A tile (row tile) once: 16B vector loads, 8 per thread
    #pragma unroll
    for (int t = 0; t < 8; t++) {
        int idx = t * 256 + tid;
        int r = idx >> 4, c8 = (idx & 15) << 3;
        *(uint4*)(&As[r * SKEW + c8]) = *(const uint4*)(&g_Ebf[(rowbase + r) * DK + c8]);
    }

    float z0 = 0.f, z1 = 0.f, z2 = 0.f, z3 = 0.f; // rows +0,+8,+16,+24 of wm*32+(lane>>2)

    for (int jt = 0; jt < JT_PER_BLK; jt++) {
        const int jbase = blockIdx.y * (JT_PER_BLK * 128) + jt * 128;
        __syncthreads(); // A visible (1st iter), Bs reusable (later iters)
        #pragma unroll
        for (int t = 0; t < 8; t++) {
            int idx = t * 256 + tid;
            int r = idx >> 4, c8 = (idx & 15) << 3;
            *(uint4*)(&Bs[r * SKEW + c8]) = *(const uint4*)(&g_Ebf[(jbase + r) * DK + c8]);
        }
        __syncthreads();

        float acc[2][8][4];
        #pragma unroll
        for (int mt = 0; mt < 2; mt++)
            #pragma unroll
            for (int nt = 0; nt < 8; nt++)
                #pragma unroll
                for (int q = 0; q < 4; q++) acc[mt][nt][q] = 0.f;

        #pragma unroll
        for (int kc = 0; kc < 8; kc++) {
            uint32_t a[2][4];
            #pragma unroll
            for (int mt = 0; mt < 2; mt++) {
                int r = wm * 32 + mt * 16 + (lane & 15);
                ldsm_x4(a[mt], &As[r * SKEW + kc * 16 + ((lane >> 4) << 3)]);
            }
            uint32_t b[8][2];
            #pragma unroll
            for (int nt = 0; nt < 8; nt++) {
                int jr = wn * 64 + nt * 8 + (lane & 7);
                ldsm_x2(b[nt], &Bs[jr * SKEW + kc * 16 + (((lane >> 3) & 1) << 3)]);
            }
            #pragma unroll
            for (int mt = 0; mt < 2; mt++)
                #pragma unroll
                for (int nt = 0; nt < 8; nt++)
                    mma16816(acc[mt][nt], a[mt], b[nt]);
        }

        // exp((dot-1)/T) accumulate, masking the diagonal
        #pragma unroll
        for (int mt = 0; mt < 2; mt++) {
            int r0 = rowbase + wm * 32 + mt * 16 + (lane >> 2);
            #pragma unroll
            for (int nt = 0; nt < 8; nt++) {
                int c0 = jbase + wn * 64 + nt * 8 + ((lane & 3) << 1);
                float e0 = (r0     == c0    ) ? 0.f : __expf((acc[mt][nt][0] - 1.0f) * INV_T);
                float e1 = (r0     == c0 + 1) ? 0.f : __expf((acc[mt][nt][1] - 1.0f) * INV_T);
                float e2 = (r0 + 8 == c0    ) ? 0.f : __expf((acc[mt][nt][2] - 1.0f) * INV_T);
                float e3 = (r0 + 8 == c0 + 1) ? 0.f : __expf((acc[mt][nt][3] - 1.0f) * INV_T);
                if (mt == 0) { z0 += e0 + e1; z1 += e2 + e3; }
                else         { z2 += e0 + e1; z3 += e2 + e3; }
            }
        }
    }

    // reduce across the 4 lanes sharing a row group, then atomic to global
    #pragma unroll
    for (int s = 1; s < 4; s <<= 1) {
        z0 += __shfl_xor_sync(0xffffffffu, z0, s);
        z1 += __shfl_xor_sync(0xffffffffu, z1, s);
        z2 += __shfl_xor_sync(0xffffffffu, z2, s);
        z3 += __shfl_xor_sync(0xffffffffu, z3, s);
    }
    if ((lane & 3) == 0) {
        int r = rowbase + wm * 32 + (lane >> 2);
        atomicAdd(&g_Z[r],      z0);
        atomicAdd(&g_Z[r + 8],  z1);
        atomicAdd(&g_Z[r + 16], z2);
        atomicAdd(&g_Z[r + 24], z3);
    }
}

// ---------------- K3: per-row finalize ----------------
// row_mean = ((e_i . S_c - e_i . e_i)/T) / pos_cnt - (M + log Z_i)
__global__ void k_final(const float* __restrict__ E) {
    int row  = blockIdx.x * 8 + (threadIdx.x >> 5);
    int lane = threadIdx.x & 31;
    if (row >= BN) return;
    int c = g_lab[row];
    int pcnt = g_cnt[c] - 1;
    const float* e = E + row * DK;
    const float* s = g_S + c * DK;
    float dS = 0.f, dE = 0.f;
    #pragma unroll
    for (int t = 0; t < 4; t++) {
        float ev = e[lane + 32 * t];
        dS += ev * s[lane + 32 * t];
        dE += ev * ev;
    }
    #pragma unroll
    for (int sh = 16; sh; sh >>= 1) {
        dS += __shfl_xor_sync(0xffffffffu, dS, sh);
        dE += __shfl_xor_sync(0xffffffffu, dE, sh);
    }
    if (lane == 0 && pcnt > 0) {
        float lse = INV_T + logf(g_Z[row]);
        float rm  = (dS - dE) * INV_T / (float)pcnt - lse;
        atomicAdd(&g_num, rm);
        atomicAdd(&g_den, 1);
    }
}

// ---------------- K4: scalar write ----------------
__global__ void k_write(float* __restrict__ out) {
    int den = g_den;
    out[0] = -g_num / (float)(den > 0 ? den : 1);
}

// ---------------- launch ----------------
extern "C" void kernel_launch(void* const* d_in, const int* in_sizes, int n_in,
                              void* d_out, int out_size) {
    const float* E   = (const float*)d_in[0];
    const void*  lab = d_in[1];
    float*       out = (float*)d_out;

    (void)in_sizes; (void)n_in; (void)out_size;

    cudaFuncSetAttribute(k_main, cudaFuncAttributeMaxDynamicSharedMemorySize, K2_SMEM);

    k_init  <<<(BN * DK + 255) / 256, 256>>>(E);
    k_detect<<<(BN + 255) / 256, 256>>>((const int*)lab);
    k_norm  <<<(BN + 255) / 256, 256>>>(lab);
    k_csum  <<<(BN * DK + 255) / 256, 256>>>(E);
    k_main  <<<dim3(64, 8), 256, K2_SMEM>>>();
    k_final <<<(BN + 7) / 8, 256>>>(E);
    k_write <<<1, 1>>>(out);
}

// round 5
// speedup vs baseline: 1.2321x; 1.2321x over previous
#include <cuda_runtime.h>
#include <cuda_bf16.h>
#include <cstdint>

// ---------------- problem constants ----------------
#define BN 8192
#define DK 128
#define NCLS 2048
constexpr float INV_T = 1.0f / 0.07f;
// exp((v-1)*INV_T) == exp2(v*C1 + C0)
constexpr float C1 = 14.2857142857f * 1.4426950408889634f;   // INV_T * log2(e)
constexpr float C0 = -14.2857142857f * 1.4426950408889634f;

// ---------------- device scratch ----------------
__device__ __nv_bfloat16 g_Ebf[BN * DK];
__device__ float g_S[NCLS * DK];
__device__ int   g_cnt[NCLS];
__device__ float g_Z[BN];
__device__ int   g_lab[BN];
__device__ float g_num;
__device__ int   g_den;
__device__ int   g_odd = 0;   // label dtype flag; data-monotone, replay-stable

// ---------------- K0: vectorized convert + zero + dtype detect ----------------
__global__ void k_init(const float4* __restrict__ E4, const int* __restrict__ lab32) {
    int idx = blockIdx.x * blockDim.x + threadIdx.x;   // 262144 threads
    if (idx < BN * DK / 4) {
        float4 v = E4[idx];
        __nv_bfloat162* d = (__nv_bfloat162*)(g_Ebf + 4 * (size_t)idx);
        d[0] = __floats2bfloat162_rn(v.x, v.y);
        d[1] = __floats2bfloat162_rn(v.z, v.w);
    }
    if (idx < NCLS * DK / 4) ((float4*)g_S)[idx] = make_float4(0.f, 0.f, 0.f, 0.f);
    if (idx < NCLS) g_cnt[idx] = 0;
    if (idx < BN) {
        g_Z[idx] = 0.0f;
        // int64 LE -> odd words all zero; int32 -> some odd word nonzero (whp)
        if ((idx & 1) && lab32[idx] != 0) atomicOr(&g_odd, 1);
    }
    if (idx == 0) { g_num = 0.0f; g_den = 0; }
}

// ---------------- mma / ldmatrix / cp.async helpers ----------------
__device__ __forceinline__ uint32_t smem_u32(const void* p) {
    return (uint32_t)__cvta_generic_to_shared(p);
}
__device__ __forceinline__ void ldsm_x4(uint32_t* r, const void* p) {
    uint32_t a = smem_u32(p);
    asm volatile("ldmatrix.sync.aligned.m8n8.x4.shared.b16 {%0,%1,%2,%3}, [%4];\n"
                 : "=r"(r[0]), "=r"(r[1]), "=r"(r[2]), "=r"(r[3]) : "r"(a));
}
__device__ __forceinline__ void mma16816(float* c, const uint32_t* a, const uint32_t* b) {
    asm volatile(
        "mma.sync.aligned.m16n8k16.row.col.f32.bf16.bf16.f32 "
        "{%0,%1,%2,%3}, {%4,%5,%6,%7}, {%8,%9}, {%0,%1,%2,%3};\n"
        : "+f"(c[0]), "+f"(c[1]), "+f"(c[2]), "+f"(c[3])
        : "r"(a[0]), "r"(a[1]), "r"(a[2]), "r"(a[3]), "r"(b[0]), "r"(b[1]));
}
__device__ __forceinline__ void cpa16(uint32_t s, const void* g) {
    asm volatile("{.reg .u64 p; cvta.to.global.u64 p, %1;"
                 " cp.async.cg.shared.global [%0], [p], 16;}"
                 :: "r"(s), "l"(g) : "memory");
}
#define CPA_COMMIT() asm volatile("cp.async.commit_group;" ::: "memory")
#define CPA_WAIT(n)  asm volatile("cp.async.wait_group %0;" :: "n"(n) : "memory")

__device__ __forceinline__ float ex2f(float x) {
    float r; asm("ex2.approx.f32 %0, %1;" : "=f"(r) : "f"(x)); return r;
}

// ---------------- K2: main GEMM + streaming exp -> Z (+ fused class-sum prep) ----------------
#define SKEW 136                      // bf16 elems per smem row (272 B, 16B-aligned cols, conflict-free)
#define TILE_BYTES (128 * SKEW * 2)   // 34816
#define SM_A 0
#define SM_B0 TILE_BYTES
#define SM_B1 (2 * TILE_BYTES)
#define K2_SMEM (3 * TILE_BYTES)      // 104448 -> 2 CTAs/SM
#define JT 8

// async-copy one 128x128 bf16 tile (row-major, 16B chunks) into SKEW layout
__device__ __forceinline__ void tile_async(uint32_t dst, const __nv_bfloat16* src, int tid) {
    #pragma unroll
    for (int t = 0; t < 8; t++) {
        int idx = t * 256 + tid;
        int r = idx >> 4, cc = (idx & 15) << 3;
        cpa16(dst + (uint32_t)(r * (SKEW * 2) + cc * 2), src + r * DK + cc);
    }
}

__global__ void __launch_bounds__(256, 2) k_main(const float* __restrict__ E,
                                                 const void* __restrict__ labp) {
    extern __shared__ __align__(16) char sm[];
    const uint32_t smb = smem_u32(sm);
    const int tid = threadIdx.x, warp = tid >> 5, lane = tid & 31;
    const int wm = warp >> 2;                // 0..1 : rows wm*64 .. +64
    const int wn = warp & 3;                 // 0..3 : cols wn*32 .. +32
    const int rowbase = blockIdx.x * 128;
    const int jcol0   = blockIdx.y * (JT * 128);
    // which j-tile (if any) holds this CTA's diagonal block
    const int diag_jt = ((int)(blockIdx.x >> 3) == (int)blockIdx.y) ? (int)(blockIdx.x & 7) : -1;

    // prologue: async A + B0
    tile_async(smb + SM_A,  g_Ebf + (size_t)rowbase * DK, tid); CPA_COMMIT();
    tile_async(smb + SM_B0, g_Ebf + (size_t)jcol0   * DK, tid); CPA_COMMIT();

    // fused prep (rides under the cp.async latency): class sums + label normalize
    {
        const int cid = (int)(blockIdx.y * 64 + blockIdx.x);    // 0..511
        const int odd = g_odd;
        #pragma unroll
        for (int u = 0; u < 8; u++) {
            int idx = cid * 2048 + u * 256 + tid;               // covers BN*DK exactly
            int row = idx >> 7, d = idx & 127;
            int v = odd ? ((const int*)labp)[row]
                        : (int)(((const long long*)labp)[row]);
            if (d == 0) { g_lab[row] = v; atomicAdd(&g_cnt[v], 1); }
            atomicAdd(&g_S[v * DK + d], E[idx]);
        }
    }

    float zz[2][4][2];
    #pragma unroll
    for (int mt = 0; mt < 4; mt++) { zz[0][mt][0]=zz[0][mt][1]=zz[1][mt][0]=zz[1][mt][1]=0.f; }
    // (zz[0] unused half kept symmetric; real accum in zz[wm? no] -- use flat:)
    float z[4][2];
    #pragma unroll
    for (int mt = 0; mt < 4; mt++) { z[mt][0] = 0.f; z[mt][1] = 0.f; }

    for (int jt = 0; jt < JT; jt++) {
        const int buf = jt & 1;
        if (jt + 1 < JT) {
            tile_async(smb + (buf ? SM_B0 : SM_B1),
                       g_Ebf + (size_t)(jcol0 + (jt + 1) * 128) * DK, tid);
            CPA_COMMIT();
            CPA_WAIT(1);
        } else {
            CPA_WAIT(0);
        }
        __syncthreads();   // B(jt) visible to all

        const char* As = sm + SM_A;
        const char* Bs = sm + (buf ? SM_B1 : SM_B0);

        float acc[4][4][4];
        #pragma unroll
        for (int mt = 0; mt < 4; mt++)
            #pragma unroll
            for (int nt = 0; nt < 4; nt++)
                #pragma unroll
                for (int q = 0; q < 4; q++) acc[mt][nt][q] = 0.f;

        #pragma unroll
        for (int kc = 0; kc < 8; kc++) {
            uint32_t a[4][4];
            #pragma unroll
            for (int mt = 0; mt < 4; mt++) {
                int r = wm * 64 + mt * 16 + (lane & 15);
                ldsm_x4(a[mt], As + r * (SKEW * 2) + (kc * 16 + ((lane >> 4) << 3)) * 2);
            }
            uint32_t b[4][2];
            #pragma unroll
            for (int np = 0; np < 2; np++) {
                int jr   = wn * 32 + np * 16 + ((lane >> 4) << 3) + (lane & 7);
                int col8 = kc * 16 + (((lane >> 3) & 1) << 3);
                uint32_t r4[4];
                ldsm_x4(r4, Bs + jr * (SKEW * 2) + col8 * 2);
                b[2*np][0]   = r4[0]; b[2*np][1]   = r4[1];
                b[2*np+1][0] = r4[2]; b[2*np+1][1] = r4[3];
            }
            #pragma unroll
            for (int mt = 0; mt < 4; mt++)
                #pragma unroll
                for (int nt = 0; nt < 4; nt++)
                    mma16816(acc[mt][nt], a[mt], b[nt]);
        }

        // epilogue: z += exp2(v*C1+C0), diagonal masked only where needed
        if (jt == diag_jt) {
            const int rb = rowbase + wm * 64 + (lane >> 2);
            const int cb = jcol0 + jt * 128 + wn * 32 + ((lane & 3) << 1);
            #pragma unroll
            for (int mt = 0; mt < 4; mt++)
                #pragma unroll
                for (int nt = 0; nt < 4; nt++)
                    #pragma unroll
                    for (int q = 0; q < 4; q++) {
                        int row = rb + mt * 16 + ((q >> 1) << 3);
                        int col = cb + nt * 8 + (q & 1);
                        float e = ex2f(fmaf(acc[mt][nt][q], C1, C0));
                        if (row == col) e = 0.0f;
                        z[mt][q >> 1] += e;
                    }
        } else {
            #pragma unroll
            for (int mt = 0; mt < 4; mt++)
                #pragma unroll
                for (int nt = 0; nt < 4; nt++) {
                    z[mt][0] += ex2f(fmaf(acc[mt][nt][0], C1, C0));
                    z[mt][0] += ex2f(fmaf(acc[mt][nt][1], C1, C0));
                    z[mt][1] += ex2f(fmaf(acc[mt][nt][2], C1, C0));
                    z[mt][1] += ex2f(fmaf(acc[mt][nt][3], C1, C0));
                }
        }
        __syncthreads();   // all reads of Bs done before next prefetch overwrites
    }

    // reduce over the 4 lanes sharing each row, then atomics
    #pragma unroll
    for (int mt = 0; mt < 4; mt++) {
        #pragma unroll
        for (int h = 0; h < 2; h++) {
            z[mt][h] += __shfl_xor_sync(0xffffffffu, z[mt][h], 1);
            z[mt][h] += __shfl_xor_sync(0xffffffffu, z[mt][h], 2);
        }
    }
    if ((lane & 3) == 0) {
        #pragma unroll
        for (int mt = 0; mt < 4; mt++) {
            int r = rowbase + wm * 64 + mt * 16 + (lane >> 2);
            atomicAdd(&g_Z[r],     z[mt][0]);
            atomicAdd(&g_Z[r + 8], z[mt][1]);
        }
    }
}

// ---------------- K3: per-row finalize ----------------
__global__ void k_final(const float* __restrict__ E) {
    int row  = blockIdx.x * 8 + (threadIdx.x >> 5);
    int lane = threadIdx.x & 31;
    if (row >= BN) return;
    int c = g_lab[row];
    int pcnt = g_cnt[c] - 1;
    const float* e = E + row * DK;
    const float* s = g_S + c * DK;
    float dS = 0.f, dE = 0.f;
    #pragma unroll
    for (int t = 0; t < 4; t++) {
        float ev = e[lane + 32 * t];
        dS += ev * s[lane + 32 * t];
        dE += ev * ev;
    }
    #pragma unroll
    for (int sh = 16; sh; sh >>= 1) {
        dS += __shfl_xor_sync(0xffffffffu, dS, sh);
        dE += __shfl_xor_sync(0xffffffffu, dE, sh);
    }
    if (lane == 0 && pcnt > 0) {
        float lse = INV_T + logf(g_Z[row]);
        float rm  = (dS - dE) * INV_T / (float)pcnt - lse;
        atomicAdd(&g_num, rm);
        atomicAdd(&g_den, 1);
    }
}

// ---------------- K4: scalar write ----------------
__global__ void k_write(float* __restrict__ out) {
    int den = g_den;
    out[0] = -g_num / (float)(den > 0 ? den : 1);
}

// ---------------- launch ----------------
extern "C" void kernel_launch(void* const* d_in, const int* in_sizes, int n_in,
                              void* d_out, int out_size) {
    const float* E   = (const float*)d_in[0];
    const void*  lab = d_in[1];
    float*       out = (float*)d_out;
    (void)in_sizes; (void)n_in; (void)out_size;

    cudaFuncSetAttribute(k_main, cudaFuncAttributeMaxDynamicSharedMemorySize, K2_SMEM);

    k_init <<<(BN * DK / 4 + 255) / 256, 256>>>((const float4*)E, (const int*)lab);
    k_main <<<dim3(64, 8), 256, K2_SMEM>>>(E, lab);
    k_final<<<(BN + 7) / 8, 256>>>(E);
    k_write<<<1, 1>>>(out);
}

// round 6
// speedup vs baseline: 1.6894x; 1.3712x over previous
#include <cuda_runtime.h>
#include <cuda_bf16.h>
#include <cstdint>

// ---------------- problem constants ----------------
#define BN 8192
#define DK 128
#define NCLS 2048
constexpr float INV_T = 1.0f / 0.07f;
// exp((v-1)*INV_T) == exp2(v*C1 + C0)
constexpr float C1 = 14.2857142857f * 1.4426950408889634f;
constexpr float C0 = -14.2857142857f * 1.4426950408889634f;

// ---------------- device scratch ----------------
__device__ __nv_bfloat16 g_Ebf[BN * DK];
__device__ float g_S[NCLS * DK];
__device__ int   g_cnt[NCLS];
__device__ float g_Z[BN];
__device__ int   g_lab[BN];
__device__ float g_num;
__device__ int   g_den;
__device__ unsigned g_done;
__device__ int   g_odd = 0;   // label dtype flag; data-monotone, replay-stable

// ---------------- K0: vectorized convert + zero + dtype detect ----------------
__global__ void k_init(const float4* __restrict__ E4, const int* __restrict__ lab32) {
    int idx = blockIdx.x * blockDim.x + threadIdx.x;   // 262144 threads
    if (idx < BN * DK / 4) {
        float4 v = E4[idx];
        __nv_bfloat162* d = (__nv_bfloat162*)(g_Ebf + 4 * (size_t)idx);
        d[0] = __floats2bfloat162_rn(v.x, v.y);
        d[1] = __floats2bfloat162_rn(v.z, v.w);
    }
    if (idx < NCLS * DK / 4) ((float4*)g_S)[idx] = make_float4(0.f, 0.f, 0.f, 0.f);
    if (idx < NCLS) g_cnt[idx] = 0;
    if (idx < BN) {
        g_Z[idx] = 0.0f;
        if ((idx & 1) && lab32[idx] != 0) atomicOr(&g_odd, 1);
    }
    if (idx == 0) { g_num = 0.0f; g_den = 0; g_done = 0; }
}

// ---------------- mma / ldmatrix / cp.async helpers ----------------
__device__ __forceinline__ uint32_t smem_u32(const void* p) {
    return (uint32_t)__cvta_generic_to_shared(p);
}
__device__ __forceinline__ void ldsm_x4(uint32_t* r, const void* p) {
    uint32_t a = smem_u32(p);
    asm volatile("ldmatrix.sync.aligned.m8n8.x4.shared.b16 {%0,%1,%2,%3}, [%4];\n"
                 : "=r"(r[0]), "=r"(r[1]), "=r"(r[2]), "=r"(r[3]) : "r"(a));
}
__device__ __forceinline__ void mma16816(float* c, const uint32_t* a, const uint32_t* b) {
    asm volatile(
        "mma.sync.aligned.m16n8k16.row.col.f32.bf16.bf16.f32 "
        "{%0,%1,%2,%3}, {%4,%5,%6,%7}, {%8,%9}, {%0,%1,%2,%3};\n"
        : "+f"(c[0]), "+f"(c[1]), "+f"(c[2]), "+f"(c[3])
        : "r"(a[0]), "r"(a[1]), "r"(a[2]), "r"(a[3]), "r"(b[0]), "r"(b[1]));
}
__device__ __forceinline__ void cpa16(uint32_t s, const void* g) {
    asm volatile("{.reg .u64 p; cvta.to.global.u64 p, %1;"
                 " cp.async.cg.shared.global [%0], [p], 16;}"
                 :: "r"(s), "l"(g) : "memory");
}
#define CPA_COMMIT() asm volatile("cp.async.commit_group;" ::: "memory")
#define CPA_WAIT(n)  asm volatile("cp.async.wait_group %0;" :: "n"(n) : "memory")

__device__ __forceinline__ float ex2f(float x) {
    float r; asm("ex2.approx.f32 %0, %1;" : "=f"(r) : "f"(x)); return r;
}

// ---------------- K2: symmetric GEMM + streaming exp -> Z ----------------
// Symmetry: tile (bi,bj) with d=(bj-bi)&63 in {0..31} (+d=32 iff bi<32) covers
// every unordered pair once; off-diagonal tiles feed BOTH row sums (Z[i]) and
// column sums (Z[j]). 2080 tiles instead of 4096.
#define SKEW 136
#define TILE_BYTES (128 * SKEW * 2)   // 34816
#define SM_A 0
#define SM_B0 TILE_BYTES
#define SM_B1 (2 * TILE_BYTES)
#define K2_SMEM (3 * TILE_BYTES)      // 104448 -> 2 CTAs/SM

__device__ __forceinline__ void tile_async(uint32_t dst, const __nv_bfloat16* src, int tid) {
    #pragma unroll
    for (int t = 0; t < 8; t++) {
        int idx = t * 256 + tid;
        int r = idx >> 4, cc = (idx & 15) << 3;
        cpa16(dst + (uint32_t)(r * (SKEW * 2) + cc * 2), src + r * DK + cc);
    }
}

__global__ void __launch_bounds__(256, 2) k_main(const float* __restrict__ E,
                                                 const void* __restrict__ labp) {
    extern __shared__ __align__(16) char sm[];
    const uint32_t smb = smem_u32(sm);
    const int tid = threadIdx.x, warp = tid >> 5, lane = tid & 31;
    const int wm = warp >> 2;                // 0..1 : rows wm*64..+64
    const int wn = warp & 3;                 // 0..3 : cols wn*32..+32
    const int bi = blockIdx.x;               // 0..63
    const int q  = blockIdx.y;               // 0..3
    const int rowbase = bi * 128;
    const int nd = (q == 3 && bi < 32) ? 9 : 8;   // distances this CTA owns
    #define DVAL(t) ((t) < 8 ? q * 8 + (t) : 32)
    #define JBASE(t) ((((bi + DVAL(t)) & 63)) * 128)

    // prologue: async A + first B
    tile_async(smb + SM_A,  g_Ebf + (size_t)rowbase * DK, tid); CPA_COMMIT();
    tile_async(smb + SM_B0, g_Ebf + (size_t)JBASE(0) * DK, tid); CPA_COMMIT();

    // fused prep (rides under cp.async latency): class sums + label normalize
    {
        const int cid = q * 64 + bi;                 // 0..255
        const int odd = g_odd;
        #pragma unroll
        for (int u = 0; u < 16; u++) {
            int idx = cid * 4096 + u * 256 + tid;    // covers BN*DK exactly
            int row = idx >> 7, d = idx & 127;
            int v = odd ? ((const int*)labp)[row]
                        : (int)(((const long long*)labp)[row]);
            if (d == 0) { g_lab[row] = v; atomicAdd(&g_cnt[v], 1); }
            atomicAdd(&g_S[v * DK + d], E[idx]);
        }
    }

    float z[4][2];
    #pragma unroll
    for (int mt = 0; mt < 4; mt++) { z[mt][0] = 0.f; z[mt][1] = 0.f; }

    for (int t = 0; t < nd; t++) {
        const int buf = t & 1;
        const int dv = DVAL(t);
        const int jbase = JBASE(t);
        if (t + 1 < nd) {
            tile_async(smb + (buf ? SM_B0 : SM_B1),
                       g_Ebf + (size_t)JBASE(t + 1) * DK, tid);
            CPA_COMMIT();
            CPA_WAIT(1);
        } else {
            CPA_WAIT(0);
        }
        __syncthreads();

        const char* As = sm + SM_A;
        const char* Bs = sm + (buf ? SM_B1 : SM_B0);

        float acc[4][4][4];
        #pragma unroll
        for (int mt = 0; mt < 4; mt++)
            #pragma unroll
            for (int nt = 0; nt < 4; nt++)
                #pragma unroll
                for (int p = 0; p < 4; p++) acc[mt][nt][p] = 0.f;

        #pragma unroll
        for (int kc = 0; kc < 8; kc++) {
            uint32_t a[4][4];
            #pragma unroll
            for (int mt = 0; mt < 4; mt++) {
                int r = wm * 64 + mt * 16 + (lane & 15);
                ldsm_x4(a[mt], As + r * (SKEW * 2) + (kc * 16 + ((lane >> 4) << 3)) * 2);
            }
            uint32_t b[4][2];
            #pragma unroll
            for (int np = 0; np < 2; np++) {
                int jr   = wn * 32 + np * 16 + ((lane >> 4) << 3) + (lane & 7);
                int col8 = kc * 16 + (((lane >> 3) & 1) << 3);
                uint32_t r4[4];
                ldsm_x4(r4, Bs + jr * (SKEW * 2) + col8 * 2);
                b[2*np][0]   = r4[0]; b[2*np][1]   = r4[1];
                b[2*np+1][0] = r4[2]; b[2*np+1][1] = r4[3];
            }
            #pragma unroll
            for (int mt = 0; mt < 4; mt++)
                #pragma unroll
                for (int nt = 0; nt < 4; nt++)
                    mma16816(acc[mt][nt], a[mt], b[nt]);
        }

        if (dv == 0) {
            // diagonal tile: full tile lives here, row sums only, mask i==j
            const int rb = rowbase + wm * 64 + (lane >> 2);
            const int cb = jbase + wn * 32 + ((lane & 3) << 1);
            #pragma unroll
            for (int mt = 0; mt < 4; mt++)
                #pragma unroll
                for (int nt = 0; nt < 4; nt++)
                    #pragma unroll
                    for (int p = 0; p < 4; p++) {
                        int row = rb + mt * 16 + ((p >> 1) << 3);
                        int col = cb + nt * 8 + (p & 1);
                        float e = ex2f(fmaf(acc[mt][nt][p], C1, C0));
                        if (row == col) e = 0.0f;
                        z[mt][p >> 1] += e;
                    }
        } else {
            // off-diagonal: row sums into z, column sums flushed to Z[jbase..]
            float ca[4][2];
            #pragma unroll
            for (int nt = 0; nt < 4; nt++) { ca[nt][0] = 0.f; ca[nt][1] = 0.f; }
            #pragma unroll
            for (int mt = 0; mt < 4; mt++)
                #pragma unroll
                for (int nt = 0; nt < 4; nt++) {
                    float e0 = ex2f(fmaf(acc[mt][nt][0], C1, C0));
                    float e1 = ex2f(fmaf(acc[mt][nt][1], C1, C0));
                    float e2 = ex2f(fmaf(acc[mt][nt][2], C1, C0));
                    float e3 = ex2f(fmaf(acc[mt][nt][3], C1, C0));
                    z[mt][0] += e0 + e1;
                    z[mt][1] += e2 + e3;
                    ca[nt][0] += e0 + e2;
                    ca[nt][1] += e1 + e3;
                }
            // reduce col sums across the 8 row-lanes (xor 4,8,16)
            #pragma unroll
            for (int nt = 0; nt < 4; nt++)
                #pragma unroll
                for (int p = 0; p < 2; p++) {
                    float v = ca[nt][p];
                    v += __shfl_xor_sync(0xffffffffu, v, 4);
                    v += __shfl_xor_sync(0xffffffffu, v, 8);
                    v += __shfl_xor_sync(0xffffffffu, v, 16);
                    ca[nt][p] = v;
                }
            if (lane < 4) {
                const int cb = jbase + wn * 32 + lane * 2;
                #pragma unroll
                for (int nt = 0; nt < 4; nt++) {
                    atomicAdd(&g_Z[cb + nt * 8],     ca[nt][0]);
                    atomicAdd(&g_Z[cb + nt * 8 + 1], ca[nt][1]);
                }
            }
        }
        __syncthreads();   // Bs reads done before next prefetch lands
    }

    // row-sum reduce over the 4 col-lanes, then atomics
    #pragma unroll
    for (int mt = 0; mt < 4; mt++)
        #pragma unroll
        for (int h = 0; h < 2; h++) {
            z[mt][h] += __shfl_xor_sync(0xffffffffu, z[mt][h], 1);
            z[mt][h] += __shfl_xor_sync(0xffffffffu, z[mt][h], 2);
        }
    if ((lane & 3) == 0) {
        #pragma unroll
        for (int mt = 0; mt < 4; mt++) {
            int r = rowbase + wm * 64 + mt * 16 + (lane >> 2);
            atomicAdd(&g_Z[r],     z[mt][0]);
            atomicAdd(&g_Z[r + 8], z[mt][1]);
        }
    }
}

// ---------------- K3: per-row finalize + fused scalar write ----------------
__global__ void k_final(const float* __restrict__ E, float* __restrict__ out) {
    int row  = blockIdx.x * 8 + (threadIdx.x >> 5);
    int lane = threadIdx.x & 31;
    __shared__ bool amLast;
    if (row < BN) {
        int c = g_lab[row];
        int pcnt = g_cnt[c] - 1;
        const float* e = E + row * DK;
        const float* s = g_S + c * DK;
        float dS = 0.f, dE = 0.f;
        #pragma unroll
        for (int t = 0; t < 4; t++) {
            float ev = e[lane + 32 * t];
            dS += ev * s[lane + 32 * t];
            dE += ev * ev;
        }
        #pragma unroll
        for (int sh = 16; sh; sh >>= 1) {
            dS += __shfl_xor_sync(0xffffffffu, dS, sh);
            dE += __shfl_xor_sync(0xffffffffu, dE, sh);
        }
        if (lane == 0 && pcnt > 0) {
            float lse = INV_T + logf(g_Z[row]);
            float rm  = (dS - dE) * INV_T / (float)pcnt - lse;
            atomicAdd(&g_num, rm);
            atomicAdd(&g_den, 1);
        }
    }
    __threadfence();
    __syncthreads();
    if (threadIdx.x == 0) {
        unsigned tkt = atomicAdd(&g_done, 1u);
        amLast = (tkt == gridDim.x - 1);
    }
    __syncthreads();
    if (amLast && threadIdx.x == 0) {
        float num = *(volatile float*)&g_num;
        int   den = *(volatile int*)&g_den;
        out[0] = -num / (float)(den > 0 ? den : 1);
    }
}

// ---------------- launch ----------------
extern "C" void kernel_launch(void* const* d_in, const int* in_sizes, int n_in,
                              void* d_out, int out_size) {
    const float* E   = (const float*)d_in[0];
    const void*  lab = d_in[1];
    float*       out = (float*)d_out;
    (void)in_sizes; (void)n_in; (void)out_size;

    cudaFuncSetAttribute(k_main, cudaFuncAttributeMaxDynamicSharedMemorySize, K2_SMEM);

    k_init <<<(BN * DK / 4 + 255) / 256, 256>>>((const float4*)E, (const int*)lab);
    k_main <<<dim3(64, 4), 256, K2_SMEM>>>(E, lab);
    k_final<<<(BN + 7) / 8, 256>>>(E, out);
}

// round 7
// speedup vs baseline: 1.7585x; 1.0409x over previous
#include <cuda_runtime.h>
#include <cuda_bf16.h>
#include <cstdint>

// ---------------- problem constants ----------------
#define BN 8192
#define DK 128
#define NCLS 2048
constexpr float INV_T = 1.0f / 0.07f;
// exp((v-1)*INV_T) == exp2(v*C1 + C0); +15 exponent shift keeps fp16 normal
constexpr float C1  = 14.2857142857f * 1.4426950408889634f;
constexpr float C0S = -14.2857142857f * 1.4426950408889634f + 15.0f;
constexpr float SCALE = 1.0f / 32768.0f;     // 2^-15, undo the shift

// ---------------- device scratch ----------------
__device__ __nv_bfloat16 g_Ebf[BN * DK];
__device__ float g_S[NCLS * DK];
__device__ int   g_cnt[NCLS];
__device__ float g_Z[BN];
__device__ int   g_lab[BN];
__device__ float g_num;
__device__ int   g_den;
__device__ unsigned g_done;
__device__ int   g_odd = 0;   // label dtype flag; data-monotone, replay-stable

// ---------------- K0: vectorized convert + zero + dtype detect ----------------
__global__ void k_init(const float4* __restrict__ E4, const int* __restrict__ lab32) {
    int idx = blockIdx.x * blockDim.x + threadIdx.x;   // 131072 threads, 2 f4 each
    #pragma unroll
    for (int h = 0; h < 2; h++) {
        int i = idx + h * 131072;
        float4 v = E4[i];
        __nv_bfloat162* d = (__nv_bfloat162*)(g_Ebf + 4 * (size_t)i);
        d[0] = __floats2bfloat162_rn(v.x, v.y);
        d[1] = __floats2bfloat162_rn(v.z, v.w);
    }
    if (idx < NCLS * DK / 4) ((float4*)g_S)[idx] = make_float4(0.f, 0.f, 0.f, 0.f);
    if (idx < NCLS) g_cnt[idx] = 0;
    if (idx < BN) {
        g_Z[idx] = 0.0f;
        if ((idx & 1) && lab32[idx] != 0) atomicOr(&g_odd, 1);
    }
    if (idx == 0) { g_num = 0.0f; g_den = 0; g_done = 0; }
}

// ---------------- asm helpers ----------------
__device__ __forceinline__ uint32_t smem_u32(const void* p) {
    return (uint32_t)__cvta_generic_to_shared(p);
}
__device__ __forceinline__ void ldsm_x4(uint32_t* r, const void* p) {
    uint32_t a = smem_u32(p);
    asm volatile("ldmatrix.sync.aligned.m8n8.x4.shared.b16 {%0,%1,%2,%3}, [%4];\n"
                 : "=r"(r[0]), "=r"(r[1]), "=r"(r[2]), "=r"(r[3]) : "r"(a));
}
__device__ __forceinline__ void mma16816(float* c, const uint32_t* a, const uint32_t* b) {
    asm volatile(
        "mma.sync.aligned.m16n8k16.row.col.f32.bf16.bf16.f32 "
        "{%0,%1,%2,%3}, {%4,%5,%6,%7}, {%8,%9}, {%0,%1,%2,%3};\n"
        : "+f"(c[0]), "+f"(c[1]), "+f"(c[2]), "+f"(c[3])
        : "r"(a[0]), "r"(a[1]), "r"(a[2]), "r"(a[3]), "r"(b[0]), "r"(b[1]));
}
__device__ __forceinline__ void cpa16(uint32_t s, const void* g) {
    asm volatile("{.reg .u64 p; cvta.to.global.u64 p, %1;"
                 " cp.async.cg.shared.global [%0], [p], 16;}"
                 :: "r"(s), "l"(g) : "memory");
}
#define CPA_COMMIT() asm volatile("cp.async.commit_group;" ::: "memory")
#define CPA_WAIT0()  asm volatile("cp.async.wait_group 0;" ::: "memory")

__device__ __forceinline__ float ex2f(float x) {
    float r; asm("ex2.approx.f32 %0, %1;" : "=f"(r) : "f"(x)); return r;
}
__device__ __forceinline__ uint32_t pack_h2(float hi, float lo) {
    uint32_t r; asm("cvt.rn.f16x2.f32 %0, %1, %2;" : "=r"(r) : "f"(hi), "f"(lo));
    return r;   // d.hi = cvt(hi), d.lo = cvt(lo)
}
__device__ __forceinline__ uint32_t ex2h2(uint32_t x) {
    uint32_t r; asm("ex2.approx.f16x2 %0, %1;" : "=r"(r) : "r"(x)); return r;
}
__device__ __forceinline__ uint32_t hadd2(uint32_t a, uint32_t b) {
    uint32_t r; asm("add.f16x2 %0, %1, %2;" : "=r"(r) : "r"(a), "r"(b)); return r;
}
__device__ __forceinline__ void unpk(uint32_t h2, float& lo, float& hi) {
    asm("{.reg .f16 l, h; mov.b32 {l, h}, %2;"
        " cvt.f32.f16 %0, l; cvt.f32.f16 %1, h;}"
        : "=f"(lo), "=f"(hi) : "r"(h2));
}

// ---------------- K2: symmetric GEMM + streaming exp -> Z ----------------
// tile (bi, bi+d), d = q*8+t (q=3 also d=32 for bi<32): 2080 tiles.
#define SKEW 136
#define TILE_BYTES (128 * SKEW * 2)   // 34816
#define SM_A 0
#define SM_B0 TILE_BYTES
#define SM_B1 (2 * TILE_BYTES)
#define K2_SMEM (3 * TILE_BYTES)      // 104448 -> 2 CTAs/SM

__device__ __forceinline__ void tile_async(uint32_t dst, const __nv_bfloat16* src, int tid) {
    #pragma unroll
    for (int t = 0; t < 8; t++) {
        int idx = t * 256 + tid;
        int r = idx >> 4, cc = (idx & 15) << 3;
        cpa16(dst + (uint32_t)(r * (SKEW * 2) + cc * 2), src + r * DK + cc);
    }
}

__global__ void __launch_bounds__(256, 2) k_main(const float* __restrict__ E,
                                                 const void* __restrict__ labp) {
    extern __shared__ __align__(16) char sm[];
    const uint32_t smb = smem_u32(sm);
    const int tid = threadIdx.x, warp = tid >> 5, lane = tid & 31;
    const int wm = warp >> 2;                // 0..1 : rows wm*64..+64
    const int wn = warp & 3;                 // 0..3 : cols wn*32..+32
    const int bi = blockIdx.x;               // 0..63
    const int q  = blockIdx.y;               // 0..3
    const int rowbase = bi * 128;
    const int nd = (q == 3 && bi < 32) ? 9 : 8;
    #define DVAL(t) ((t) < 8 ? q * 8 + (t) : 32)
    #define JBASE(t) ((((bi + DVAL(t)) & 63)) * 128)
    const int cid = q * 64 + bi;
    const int odd = g_odd;

    // prologue: async A + first B (one group)
    tile_async(smb + SM_A,  g_Ebf + (size_t)rowbase * DK, tid);
    tile_async(smb + SM_B0, g_Ebf + (size_t)JBASE(0) * DK, tid);
    CPA_COMMIT();

    float z[4][2];
    #pragma unroll
    for (int mt = 0; mt < 4; mt++) { z[mt][0] = 0.f; z[mt][1] = 0.f; }

    for (int t = 0; t < nd; t++) {
        const int buf = t & 1;
        const int dv = DVAL(t);
        const int jbase = JBASE(t);

        CPA_WAIT0();
        __syncthreads();   // B(t) visible AND everyone done reading B(t-1)

        if (t + 1 < nd) {
            tile_async(smb + (buf ? SM_B0 : SM_B1),
                       g_Ebf + (size_t)JBASE(t + 1) * DK, tid);
            CPA_COMMIT();
        }

        const char* As = sm + SM_A;
        const char* Bs = sm + (buf ? SM_B1 : SM_B0);

        float acc[4][4][4];
        #pragma unroll
        for (int mt = 0; mt < 4; mt++)
            #pragma unroll
            for (int nt = 0; nt < 4; nt++)
                #pragma unroll
                for (int p = 0; p < 4; p++) acc[mt][nt][p] = 0.f;

        #pragma unroll
        for (int kc = 0; kc < 8; kc++) {
            uint32_t a[4][4];
            #pragma unroll
            for (int mt = 0; mt < 4; mt++) {
                int r = wm * 64 + mt * 16 + (lane & 15);
                ldsm_x4(a[mt], As + r * (SKEW * 2) + (kc * 16 + ((lane >> 4) << 3)) * 2);
            }
            uint32_t b[4][2];
            #pragma unroll
            for (int np = 0; np < 2; np++) {
                int jr   = wn * 32 + np * 16 + ((lane >> 4) << 3) + (lane & 7);
                int col8 = kc * 16 + (((lane >> 3) & 1) << 3);
                uint32_t r4[4];
                ldsm_x4(r4, Bs + jr * (SKEW * 2) + col8 * 2);
                b[2*np][0]   = r4[0]; b[2*np][1]   = r4[1];
                b[2*np+1][0] = r4[2]; b[2*np+1][1] = r4[3];
            }
            #pragma unroll
            for (int mt = 0; mt < 4; mt++)
                #pragma unroll
                for (int nt = 0; nt < 4; nt++)
                    mma16816(acc[mt][nt], a[mt], b[nt]);
        }

        if (dv == 0) {
            // diagonal tile: fp32 path, mask i==j (scaled domain)
            const int rb = rowbase + wm * 64 + (lane >> 2);
            const int cb = jbase + wn * 32 + ((lane & 3) << 1);
            #pragma unroll
            for (int mt = 0; mt < 4; mt++)
                #pragma unroll
                for (int nt = 0; nt < 4; nt++)
                    #pragma unroll
                    for (int p = 0; p < 4; p++) {
                        int row = rb + mt * 16 + ((p >> 1) << 3);
                        int col = cb + nt * 8 + (p & 1);
                        float e = ex2f(fmaf(acc[mt][nt][p], C1, C0S));
                        if (row == col) e = 0.0f;
                        z[mt][p >> 1] += e;
                    }
        } else {
            // off-diagonal: packed fp16x2 exp; row sums -> z, col sums -> Z[j]
            uint32_t zh[4][2], cah[4];
            #pragma unroll
            for (int mt = 0; mt < 4; mt++) { zh[mt][0] = 0; zh[mt][1] = 0; }
            #pragma unroll
            for (int nt = 0; nt < 4; nt++) cah[nt] = 0;

            #pragma unroll
            for (int mt = 0; mt < 4; mt++)
                #pragma unroll
                for (int nt = 0; nt < 4; nt++) {
                    float a0 = fmaf(acc[mt][nt][0], C1, C0S);
                    float a1 = fmaf(acc[mt][nt][1], C1, C0S);
                    float a2 = fmaf(acc[mt][nt][2], C1, C0S);
                    float a3 = fmaf(acc[mt][nt][3], C1, C0S);
                    uint32_t h2a = ex2h2(pack_h2(a1, a0)); // (lo=even col, hi=odd col) @ row r
                    uint32_t h2b = ex2h2(pack_h2(a3, a2)); // @ row r+8
                    zh[mt][0] = hadd2(zh[mt][0], h2a);
                    zh[mt][1] = hadd2(zh[mt][1], h2b);
                    cah[nt]   = hadd2(cah[nt], hadd2(h2a, h2b));
                }
            // fold packed row sums into fp32 accumulators
            #pragma unroll
            for (int mt = 0; mt < 4; mt++)
                #pragma unroll
                for (int h = 0; h < 2; h++) {
                    float lo, hi; unpk(zh[mt][h], lo, hi);
                    z[mt][h] += lo + hi;
                }
            // packed column reduce across the 8 row-lanes
            #pragma unroll
            for (int nt = 0; nt < 4; nt++) {
                uint32_t v = cah[nt];
                v = hadd2(v, __shfl_xor_sync(0xffffffffu, v, 4));
                v = hadd2(v, __shfl_xor_sync(0xffffffffu, v, 8));
                v = hadd2(v, __shfl_xor_sync(0xffffffffu, v, 16));
                cah[nt] = v;
            }
            if (lane < 4) {
                const int cb = jbase + wn * 32 + lane * 2;
                #pragma unroll
                for (int nt = 0; nt < 4; nt++) {
                    float lo, hi; unpk(cah[nt], lo, hi);
                    atomicAdd(&g_Z[cb + nt * 8],     lo * SCALE);
                    atomicAdd(&g_Z[cb + nt * 8 + 1], hi * SCALE);
                }
            }
        }

        // spread class-sum prep: 2 chunks per iteration, overlapped with MMA
        if (t < 8) {
            #pragma unroll
            for (int u2 = 0; u2 < 2; u2++) {
                int idx = cid * 4096 + (t * 2 + u2) * 256 + tid;
                int row = idx >> 7, d = idx & 127;
                int v = odd ? ((const int*)labp)[row]
                            : (int)(((const long long*)labp)[row]);
                if (d == 0) { g_lab[row] = v; atomicAdd(&g_cnt[v], 1); }
                atomicAdd(&g_S[v * DK + d], E[idx]);
            }
        }
    }

    // row-sum reduce over the 4 col-lanes, then scaled atomics
    #pragma unroll
    for (int mt = 0; mt < 4; mt++)
        #pragma unroll
        for (int h = 0; h < 2; h++) {
            z[mt][h] += __shfl_xor_sync(0xffffffffu, z[mt][h], 1);
            z[mt][h] += __shfl_xor_sync(0xffffffffu, z[mt][h], 2);
        }
    if ((lane & 3) == 0) {
        #pragma unroll
        for (int mt = 0; mt < 4; mt++) {
            int r = rowbase + wm * 64 + mt * 16 + (lane >> 2);
            atomicAdd(&g_Z[r],     z[mt][0] * SCALE);
            atomicAdd(&g_Z[r + 8], z[mt][1] * SCALE);
        }
    }
}

// ---------------- K3: per-row finalize + fused scalar write ----------------
__global__ void k_final(const float* __restrict__ E, float* __restrict__ out) {
    int row  = blockIdx.x * 8 + (threadIdx.x >> 5);
    int lane = threadIdx.x & 31;
    __shared__ bool amLast;
    if (row < BN) {
        int c = g_lab[row];
        int pcnt = g_cnt[c] - 1;
        const float* e = E + row * DK;
        const float* s = g_S + c * DK;
        float dS = 0.f, dE = 0.f;
        #pragma unroll
        for (int t = 0; t < 4; t++) {
            float ev = e[lane + 32 * t];
            dS += ev * s[lane + 32 * t];
            dE += ev * ev;
        }
        #pragma unroll
        for (int sh = 16; sh; sh >>= 1) {
            dS += __shfl_xor_sync(0xffffffffu, dS, sh);
            dE += __shfl_xor_sync(0xffffffffu, dE, sh);
        }
        if (lane == 0 && pcnt > 0) {
            float lse = INV_T + logf(g_Z[row]);
            float rm  = (dS - dE) * INV_T / (float)pcnt - lse;
            atomicAdd(&g_num, rm);
            atomicAdd(&g_den, 1);
        }
    }
    __threadfence();
    __syncthreads();
    if (threadIdx.x == 0) {
        unsigned tkt = atomicAdd(&g_done, 1u);
        amLast = (tkt == gridDim.x - 1);
    }
    __syncthreads();
    if (amLast && threadIdx.x == 0) {
        float num = *(volatile float*)&g_num;
        int   den = *(volatile int*)&g_den;
        out[0] = -num / (float)(den > 0 ? den : 1);
    }
}

// ---------------- launch ----------------
extern "C" void kernel_launch(void* const* d_in, const int* in_sizes, int n_in,
                              void* d_out, int out_size) {
    const float* E   = (const float*)d_in[0];
    const void*  lab = d_in[1];
    float*       out = (float*)d_out;
    (void)in_sizes; (void)n_in; (void)out_size;

    cudaFuncSetAttribute(k_main, cudaFuncAttributeMaxDynamicSharedMemorySize, K2_SMEM);

    k_init <<<512, 256>>>((const float4*)E, (const int*)lab);
    k_main <<<dim3(64, 4), 256, K2_SMEM>>>(E, lab);
    k_final<<<(BN + 7) / 8, 256>>>(E, out);
}

// round 8
// speedup vs baseline: 1.8544x; 1.0545x over previous
#include <cuda_runtime.h>
#include <cuda_bf16.h>
#include <cstdint>

// ---------------- problem constants ----------------
#define BN 8192
#define DK 128
#define NCLS 2048
constexpr float INV_T = 1.0f / 0.07f;
// exp((v-1)*INV_T) == exp2(v*C1 + C0); +15 exponent shift keeps fp16 normal
constexpr float C1  = 14.2857142857f * 1.4426950408889634f;
constexpr float C0S = -14.2857142857f * 1.4426950408889634f + 15.0f;
constexpr float SCALE = 1.0f / 32768.0f;     // 2^-15, undo the shift

#define NCTA 296          // 148 SMs x 2 CTAs: exactly one wave
#define NTILE 2080        // symmetric tile count

// ---------------- device scratch ----------------
__device__ __nv_bfloat16 g_Ebf[BN * DK];
__device__ float g_S[NCLS * DK];
__device__ int   g_cnt[NCLS];
__device__ float g_Z[BN];
__device__ int   g_lab[BN];
__device__ float g_num;
__device__ int   g_den;
__device__ unsigned g_done;
__device__ int   g_odd = 0;   // label dtype flag; data-monotone, replay-stable

// ---------------- K0: vectorized convert + zero + dtype detect (MLP=4) ----------------
__global__ void k_init(const float4* __restrict__ E4, const int* __restrict__ lab32) {
    int idx = blockIdx.x * blockDim.x + threadIdx.x;   // 65536 threads, 4 f4 each
    #pragma unroll
    for (int h = 0; h < 4; h++) {
        int i = idx + h * 65536;
        float4 v = E4[i];
        __nv_bfloat162* d = (__nv_bfloat162*)(g_Ebf + 4 * (size_t)i);
        d[0] = __floats2bfloat162_rn(v.x, v.y);
        d[1] = __floats2bfloat162_rn(v.z, v.w);
    }
    ((float4*)g_S)[idx] = make_float4(0.f, 0.f, 0.f, 0.f);  // 65536 == NCLS*DK/4
    if (idx < NCLS) g_cnt[idx] = 0;
    if (idx < BN) {
        g_Z[idx] = 0.0f;
        if ((idx & 1) && lab32[idx] != 0) atomicOr(&g_odd, 1);
    }
    if (idx == 0) { g_num = 0.0f; g_den = 0; g_done = 0; }
}

// ---------------- asm helpers ----------------
__device__ __forceinline__ uint32_t smem_u32(const void* p) {
    return (uint32_t)__cvta_generic_to_shared(p);
}
__device__ __forceinline__ void ldsm_x4(uint32_t* r, const void* p) {
    uint32_t a = smem_u32(p);
    asm volatile("ldmatrix.sync.aligned.m8n8.x4.shared.b16 {%0,%1,%2,%3}, [%4];\n"
                 : "=r"(r[0]), "=r"(r[1]), "=r"(r[2]), "=r"(r[3]) : "r"(a));
}
__device__ __forceinline__ void mma16816(float* c, const uint32_t* a, const uint32_t* b) {
    asm volatile(
        "mma.sync.aligned.m16n8k16.row.col.f32.bf16.bf16.f32 "
        "{%0,%1,%2,%3}, {%4,%5,%6,%7}, {%8,%9}, {%0,%1,%2,%3};\n"
        : "+f"(c[0]), "+f"(c[1]), "+f"(c[2]), "+f"(c[3])
        : "r"(a[0]), "r"(a[1]), "r"(a[2]), "r"(a[3]), "r"(b[0]), "r"(b[1]));
}
__device__ __forceinline__ void cpa16(uint32_t s, const void* g) {
    asm volatile("{.reg .u64 p; cvta.to.global.u64 p, %1;"
                 " cp.async.cg.shared.global [%0], [p], 16;}"
                 :: "r"(s), "l"(g) : "memory");
}
#define CPA_COMMIT() asm volatile("cp.async.commit_group;" ::: "memory")
#define CPA_WAIT0()  asm volatile("cp.async.wait_group 0;" ::: "memory")
#define CPA_WAIT1()  asm volatile("cp.async.wait_group 1;" ::: "memory")

__device__ __forceinline__ float ex2f(float x) {
    float r; asm("ex2.approx.f32 %0, %1;" : "=f"(r) : "f"(x)); return r;
}
__device__ __forceinline__ uint32_t pack_h2(float hi, float lo) {
    uint32_t r; asm("cvt.rn.f16x2.f32 %0, %1, %2;" : "=r"(r) : "f"(hi), "f"(lo));
    return r;
}
__device__ __forceinline__ uint32_t ex2h2(uint32_t x) {
    uint32_t r; asm("ex2.approx.f16x2 %0, %1;" : "=r"(r) : "r"(x)); return r;
}
__device__ __forceinline__ uint32_t hadd2(uint32_t a, uint32_t b) {
    uint32_t r; asm("add.f16x2 %0, %1, %2;" : "=r"(r) : "r"(a), "r"(b)); return r;
}
__device__ __forceinline__ void unpk(uint32_t h2, float& lo, float& hi) {
    asm("{.reg .f16 l, h; mov.b32 {l, h}, %2;"
        " cvt.f32.f16 %0, l; cvt.f32.f16 %1, h;}"
        : "=f"(lo), "=f"(hi) : "r"(h2));
}

// tile enumeration: bi<32 -> 33 distances (0..32), bi>=32 -> 32 (0..31)
__device__ __forceinline__ void decode(int g, int& bi, int& d) {
    if (g < 1056) { bi = g / 33; d = g - bi * 33; }
    else          { int h = g - 1056; bi = 32 + (h >> 5); d = h & 31; }
}

// ---------------- K2: symmetric GEMM + streaming exp -> Z ----------------
#define SKEW 136
#define TILE_BYTES (128 * SKEW * 2)   // 34816
#define SM_A 0
#define SM_B0 TILE_BYTES
#define SM_B1 (2 * TILE_BYTES)
#define K2_SMEM (3 * TILE_BYTES)      // 104448 -> 2 CTAs/SM

__device__ __forceinline__ void tile_async(uint32_t dst, const __nv_bfloat16* src, int tid) {
    #pragma unroll
    for (int t = 0; t < 8; t++) {
        int idx = t * 256 + tid;
        int r = idx >> 4, cc = (idx & 15) << 3;
        cpa16(dst + (uint32_t)(r * (SKEW * 2) + cc * 2), src + r * DK + cc);
    }
}

__device__ __forceinline__ void flush_z(float z[4][2], int rowbase, int wm, int lane) {
    #pragma unroll
    for (int mt = 0; mt < 4; mt++)
        #pragma unroll
        for (int h = 0; h < 2; h++) {
            z[mt][h] += __shfl_xor_sync(0xffffffffu, z[mt][h], 1);
            z[mt][h] += __shfl_xor_sync(0xffffffffu, z[mt][h], 2);
        }
    if ((lane & 3) == 0) {
        #pragma unroll
        for (int mt = 0; mt < 4; mt++) {
            int r = rowbase + wm * 64 + mt * 16 + (lane >> 2);
            atomicAdd(&g_Z[r],     z[mt][0] * SCALE);
            atomicAdd(&g_Z[r + 8], z[mt][1] * SCALE);
        }
    }
    #pragma unroll
    for (int mt = 0; mt < 4; mt++) { z[mt][0] = 0.f; z[mt][1] = 0.f; }
}

__global__ void __launch_bounds__(256, 2) k_main(const float* __restrict__ E,
                                                 const void* __restrict__ labp) {
    extern __shared__ __align__(16) char sm[];
    const uint32_t smb = smem_u32(sm);
    const int tid = threadIdx.x, warp = tid >> 5, lane = tid & 31;
    const int wm = warp >> 2;                // 0..1 : rows wm*64..+64
    const int wn = warp & 3;                 // 0..3 : cols wn*32..+32
    const int c  = blockIdx.x;               // 0..295
    const int g0 = (NTILE * c) / NCTA;
    const int g1 = (NTILE * (c + 1)) / NCTA; // 7 or 8 tiles
    const int odd = g_odd;

    int cur_bi, d0; decode(g0, cur_bi, d0);

    // prologue: async A + first B (one group)
    tile_async(smb + SM_A,  g_Ebf + (size_t)(cur_bi * 128) * DK, tid);
    tile_async(smb + SM_B0, g_Ebf + (size_t)(((cur_bi + d0) & 63) * 128) * DK, tid);
    CPA_COMMIT();

    float z[4][2];
    #pragma unroll
    for (int mt = 0; mt < 4; mt++) { z[mt][0] = 0.f; z[mt][1] = 0.f; }

    for (int g = g0; g < g1; g++) {
        const int it  = g - g0;
        const int buf = it & 1;
        int bi, dv; decode(g, bi, dv);
        const int jbase = ((bi + dv) & 63) * 128;

        CPA_WAIT0();
        __syncthreads();   // B(g) visible AND all reads of overwritten buffers done

        bool pend = false;
        if (bi != cur_bi) {
            flush_z(z, cur_bi * 128, wm, lane);   // rows change: flush row sums
            cur_bi = bi;
            tile_async(smb + SM_A, g_Ebf + (size_t)(bi * 128) * DK, tid);
            CPA_COMMIT();
            pend = true;
        }
        if (g + 1 < g1) {
            int nbi, ndv; decode(g + 1, nbi, ndv);
            tile_async(smb + (buf ? SM_B0 : SM_B1),
                       g_Ebf + (size_t)(((nbi + ndv) & 63) * 128) * DK, tid);
            CPA_COMMIT();
            if (pend) { CPA_WAIT1(); __syncthreads(); }   // A ready, B(g+1) in flight
        } else if (pend) {
            CPA_WAIT0(); __syncthreads();
        }

        const char* As = sm + SM_A;
        const char* Bs = sm + (buf ? SM_B1 : SM_B0);

        float acc[4][4][4];
        #pragma unroll
        for (int mt = 0; mt < 4; mt++)
            #pragma unroll
            for (int nt = 0; nt < 4; nt++)
                #pragma unroll
                for (int p = 0; p < 4; p++) acc[mt][nt][p] = 0.f;

        #pragma unroll
        for (int kc = 0; kc < 8; kc++) {
            uint32_t a[4][4];
            #pragma unroll
            for (int mt = 0; mt < 4; mt++) {
                int r = wm * 64 + mt * 16 + (lane & 15);
                ldsm_x4(a[mt], As + r * (SKEW * 2) + (kc * 16 + ((lane >> 4) << 3)) * 2);
            }
            uint32_t b[4][2];
            #pragma unroll
            for (int np = 0; np < 2; np++) {
                int jr   = wn * 32 + np * 16 + ((lane >> 4) << 3) + (lane & 7);
                int col8 = kc * 16 + (((lane >> 3) & 1) << 3);
                uint32_t r4[4];
                ldsm_x4(r4, Bs + jr * (SKEW * 2) + col8 * 2);
                b[2*np][0]   = r4[0]; b[2*np][1]   = r4[1];
                b[2*np+1][0] = r4[2]; b[2*np+1][1] = r4[3];
            }
            #pragma unroll
            for (int mt = 0; mt < 4; mt++)
                #pragma unroll
                for (int nt = 0; nt < 4; nt++)
                    mma16816(acc[mt][nt], a[mt], b[nt]);
        }

        if (dv == 0) {
            // diagonal tile: fp32 path, mask i==j (scaled domain)
            const int rb = bi * 128 + wm * 64 + (lane >> 2);
            const int cb = jbase + wn * 32 + ((lane & 3) << 1);
            #pragma unroll
            for (int mt = 0; mt < 4; mt++)
                #pragma unroll
                for (int nt = 0; nt < 4; nt++)
                    #pragma unroll
                    for (int p = 0; p < 4; p++) {
                        int row = rb + mt * 16 + ((p >> 1) << 3);
                        int col = cb + nt * 8 + (p & 1);
                        float e = ex2f(fmaf(acc[mt][nt][p], C1, C0S));
                        if (row == col) e = 0.0f;
                        z[mt][p >> 1] += e;
                    }
        } else {
            // off-diagonal: packed fp16x2 exp; row sums -> z, col sums -> Z[j]
            uint32_t zh[4][2], cah[4];
            #pragma unroll
            for (int mt = 0; mt < 4; mt++) { zh[mt][0] = 0; zh[mt][1] = 0; }
            #pragma unroll
            for (int nt = 0; nt < 4; nt++) cah[nt] = 0;

            #pragma unroll
            for (int mt = 0; mt < 4; mt++)
                #pragma unroll
                for (int nt = 0; nt < 4; nt++) {
                    float a0 = fmaf(acc[mt][nt][0], C1, C0S);
                    float a1 = fmaf(acc[mt][nt][1], C1, C0S);
                    float a2 = fmaf(acc[mt][nt][2], C1, C0S);
                    float a3 = fmaf(acc[mt][nt][3], C1, C0S);
                    uint32_t h2a = ex2h2(pack_h2(a1, a0));
                    uint32_t h2b = ex2h2(pack_h2(a3, a2));
                    zh[mt][0] = hadd2(zh[mt][0], h2a);
                    zh[mt][1] = hadd2(zh[mt][1], h2b);
                    cah[nt]   = hadd2(cah[nt], hadd2(h2a, h2b));
                }
            #pragma unroll
            for (int mt = 0; mt < 4; mt++)
                #pragma unroll
                for (int h = 0; h < 2; h++) {
                    float lo, hi; unpk(zh[mt][h], lo, hi);
                    z[mt][h] += lo + hi;
                }
            #pragma unroll
            for (int nt = 0; nt < 4; nt++) {
                uint32_t v = cah[nt];
                v = hadd2(v, __shfl_xor_sync(0xffffffffu, v, 4));
                v = hadd2(v, __shfl_xor_sync(0xffffffffu, v, 8));
                v = hadd2(v, __shfl_xor_sync(0xffffffffu, v, 16));
                cah[nt] = v;
            }
            if (lane < 4) {
                const int cb = jbase + wn * 32 + lane * 2;
                #pragma unroll
                for (int nt = 0; nt < 4; nt++) {
                    float lo, hi; unpk(cah[nt], lo, hi);
                    atomicAdd(&g_Z[cb + nt * 8],     lo * SCALE);
                    atomicAdd(&g_Z[cb + nt * 8 + 1], hi * SCALE);
                }
            }
        }

        // spread class-sum prep: 2 chunks/iter over first 7 iters (14 * 256 * 296 covers all)
        if (it < 7) {
            #pragma unroll
            for (int u2 = 0; u2 < 2; u2++) {
                int idx = c * 3584 + (it * 2 + u2) * 256 + tid;
                if (idx < BN * DK) {
                    int row = idx >> 7, d = idx & 127;
                    int v = odd ? ((const int*)labp)[row]
                                : (int)(((const long long*)labp)[row]);
                    if (d == 0) { g_lab[row] = v; atomicAdd(&g_cnt[v], 1); }
                    atomicAdd(&g_S[v * DK + d], E[idx]);
                }
            }
        }
    }

    flush_z(z, cur_bi * 128, wm, lane);
}

// ---------------- K3: per-row finalize + fused scalar write ----------------
__global__ void k_final(const float* __restrict__ E, float* __restrict__ out) {
    int row  = blockIdx.x * 8 + (threadIdx.x >> 5);
    int lane = threadIdx.x & 31;
    __shared__ bool amLast;
    if (row < BN) {
        int c = g_lab[row];
        int pcnt = g_cnt[c] - 1;
        const float* e = E + row * DK;
        const float* s = g_S + c * DK;
        float dS = 0.f, dE = 0.f;
        #pragma unroll
        for (int t = 0; t < 4; t++) {
            float ev = e[lane + 32 * t];
            dS += ev * s[lane + 32 * t];
            dE += ev * ev;
        }
        #pragma unroll
        for (int sh = 16; sh; sh >>= 1) {
            dS += __shfl_xor_sync(0xffffffffu, dS, sh);
            dE += __shfl_xor_sync(0xffffffffu, dE, sh);
        }
        if (lane == 0 && pcnt > 0) {
            float lse = INV_T + logf(g_Z[row]);
            float rm  = (dS - dE) * INV_T / (float)pcnt - lse;
            atomicAdd(&g_num, rm);
            atomicAdd(&g_den, 1);
        }
    }
    __threadfence();
    __syncthreads();
    if (threadIdx.x == 0) {
        unsigned tkt = atomicAdd(&g_done, 1u);
        amLast = (tkt == gridDim.x - 1);
    }
    __syncthreads();
    if (amLast && threadIdx.x == 0) {
        float num = *(volatile float*)&g_num;
        int   den = *(volatile int*)&g_den;
        out[0] = -num / (float)(den > 0 ? den : 1);
    }
}

// ---------------- launch ----------------
extern "C" void kernel_launch(void* const* d_in, const int* in_sizes, int n_in,
                              void* d_out, int out_size) {
    const float* E   = (const float*)d_in[0];
    const void*  lab = d_in[1];
    float*       out = (float*)d_out;
    (void)in_sizes; (void)n_in; (void)out_size;

    cudaFuncSetAttribute(k_main, cudaFuncAttributeMaxDynamicSharedMemorySize, K2_SMEM);

    k_init <<<256, 256>>>((const float4*)E, (const int*)lab);
    k_main <<<NCTA, 256, K2_SMEM>>>(E, lab);
    k_final<<<(BN + 7) / 8, 256>>>(E, out);
}